// round 4
// baseline (speedup 1.0000x reference)
#include <cuda_runtime.h>
#include <math.h>

// B=8, T=2048, D=768, QKV_OUT=2304. Reference is SINGLE-head attention over
// the full 768 dims (no head reshape), scale 1/sqrt(64) = 0.125.
#define BT 16384
#define DIM 768
#define QKVO 2304
#define SEQ 2048
#define NB 8
#define SCALE 0.125f

// Scratch (device globals: allocation-free rule)
__device__ float g_qkv[(size_t)BT * QKVO];       // 16384 x 2304 (q|k|v)
__device__ float g_scores[(size_t)NB * SEQ * SEQ]; // 8 x 2048 x 2048
__device__ float g_att[(size_t)BT * DIM];        // 16384 x 768

// ---------------------------------------------------------------------------
// Generalized SGEMM: C = alpha * A @ op(B) + bias
//   A: [M,K] row-major, lda.  op(B)=B [K,N] (NN) or B^T with B [N,K] (NT).
//   Batched via grid.z with element strides. BM=BN=128, BK=8, 256 threads,
//   8x8 per thread (4+4 split).
// ---------------------------------------------------------------------------
template<bool TRANSB, bool HASBIAS>
__global__ __launch_bounds__(256)
void gemm_kernel(const float* __restrict__ A,
                 const float* __restrict__ B,
                 const float* __restrict__ bias,
                 float* __restrict__ C,
                 int M, int N, int K,
                 int lda, int ldb, int ldc,
                 float alpha,
                 long long sA, long long sB, long long sC)
{
    const int BK = 8;
    __shared__ __align__(16) float As[BK][128];
    __shared__ __align__(16) float Bs[BK][128];

    int tid = threadIdx.x;
    int tx = tid & 15;
    int ty = tid >> 4;

    const float* Ab = A + (size_t)blockIdx.z * sA + (size_t)blockIdx.y * 128 * lda;
    const float* Bb;
    if (TRANSB)
        Bb = B + (size_t)blockIdx.z * sB + (size_t)blockIdx.x * 128 * ldb;
    else
        Bb = B + (size_t)blockIdx.z * sB + (size_t)blockIdx.x * 128;
    float* Cb = C + (size_t)blockIdx.z * sC;

    float acc[8][8];
#pragma unroll
    for (int i = 0; i < 8; i++)
#pragma unroll
        for (int j = 0; j < 8; j++) acc[i][j] = 0.0f;

    // A-tile loader: 128 rows x 8 cols, one float4 per thread
    int la_r = tid >> 1;
    int la_c = (tid & 1) * 4;
    // B-tile NN loader: 8 rows x 128 cols
    int lb_r = tid >> 5;
    int lb_c = (tid & 31) * 4;

    for (int k0 = 0; k0 < K; k0 += BK) {
        float4 a4 = *(const float4*)(Ab + (size_t)la_r * lda + k0 + la_c);
        As[la_c + 0][la_r] = a4.x;
        As[la_c + 1][la_r] = a4.y;
        As[la_c + 2][la_r] = a4.z;
        As[la_c + 3][la_r] = a4.w;
        if (TRANSB) {
            // B [N,K]: row = n (la_r), cols k0+la_c..+3 -> Bs[kk][n]
            float4 b4 = *(const float4*)(Bb + (size_t)la_r * ldb + k0 + la_c);
            Bs[la_c + 0][la_r] = b4.x;
            Bs[la_c + 1][la_r] = b4.y;
            Bs[la_c + 2][la_r] = b4.z;
            Bs[la_c + 3][la_r] = b4.w;
        } else {
            float4 b4 = *(const float4*)(Bb + (size_t)(k0 + lb_r) * ldb + lb_c);
            *(float4*)(&Bs[lb_r][lb_c]) = b4;
        }
        __syncthreads();

#pragma unroll
        for (int kk = 0; kk < BK; kk++) {
            float am[8], bn[8];
            *(float4*)&am[0] = *(const float4*)&As[kk][ty * 4];
            *(float4*)&am[4] = *(const float4*)&As[kk][ty * 4 + 64];
            *(float4*)&bn[0] = *(const float4*)&Bs[kk][tx * 4];
            *(float4*)&bn[4] = *(const float4*)&Bs[kk][tx * 4 + 64];
#pragma unroll
            for (int i = 0; i < 8; i++)
#pragma unroll
                for (int j = 0; j < 8; j++)
                    acc[i][j] = fmaf(am[i], bn[j], acc[i][j]);
        }
        __syncthreads();
    }

#pragma unroll
    for (int i = 0; i < 8; i++) {
        int row = blockIdx.y * 128 + ty * 4 + (i & 3) + (i >> 2) * 64;
#pragma unroll
        for (int jh = 0; jh < 2; jh++) {
            int col = blockIdx.x * 128 + tx * 4 + jh * 64;
            float4 r;
            r.x = alpha * acc[i][jh * 4 + 0];
            r.y = alpha * acc[i][jh * 4 + 1];
            r.z = alpha * acc[i][jh * 4 + 2];
            r.w = alpha * acc[i][jh * 4 + 3];
            if (HASBIAS) {
                r.x += bias[col + 0];
                r.y += bias[col + 1];
                r.z += bias[col + 2];
                r.w += bias[col + 3];
            }
            *(float4*)(Cb + (size_t)row * ldc + col) = r;
        }
    }
}

// ---------------------------------------------------------------------------
// Row softmax in place: 16384 rows x 2048 cols. One block (256 thr) per row.
// ---------------------------------------------------------------------------
__global__ __launch_bounds__(256)
void softmax_kernel(float* __restrict__ S)
{
    __shared__ float red[8];
    int tid = threadIdx.x;
    float* row = S + (size_t)blockIdx.x * SEQ;

    // Each thread: 2 float4 loads (positions tid*4 + it*1024)
    float4 v0 = *(const float4*)(row + tid * 4);
    float4 v1 = *(const float4*)(row + 1024 + tid * 4);

    float mx = fmaxf(fmaxf(fmaxf(v0.x, v0.y), fmaxf(v0.z, v0.w)),
                     fmaxf(fmaxf(v1.x, v1.y), fmaxf(v1.z, v1.w)));
#pragma unroll
    for (int off = 16; off > 0; off >>= 1)
        mx = fmaxf(mx, __shfl_xor_sync(0xffffffffu, mx, off));
    if ((tid & 31) == 0) red[tid >> 5] = mx;
    __syncthreads();
    if (tid < 32) {
        float t = (tid < 8) ? red[tid] : -1e30f;
#pragma unroll
        for (int off = 4; off > 0; off >>= 1)
            t = fmaxf(t, __shfl_xor_sync(0xffffffffu, t, off));
        if (tid == 0) red[0] = t;
    }
    __syncthreads();
    mx = red[0];

    v0.x = __expf(v0.x - mx); v0.y = __expf(v0.y - mx);
    v0.z = __expf(v0.z - mx); v0.w = __expf(v0.w - mx);
    v1.x = __expf(v1.x - mx); v1.y = __expf(v1.y - mx);
    v1.z = __expf(v1.z - mx); v1.w = __expf(v1.w - mx);

    float sm = v0.x + v0.y + v0.z + v0.w + v1.x + v1.y + v1.z + v1.w;
#pragma unroll
    for (int off = 16; off > 0; off >>= 1)
        sm += __shfl_xor_sync(0xffffffffu, sm, off);
    if ((tid & 31) == 0) red[tid >> 5] = sm;
    __syncthreads();
    if (tid < 32) {
        float t = (tid < 8) ? red[tid] : 0.0f;
#pragma unroll
        for (int off = 4; off > 0; off >>= 1)
            t += __shfl_xor_sync(0xffffffffu, t, off);
        if (tid == 0) red[0] = t;
    }
    __syncthreads();
    float inv = 1.0f / red[0];

    v0.x *= inv; v0.y *= inv; v0.z *= inv; v0.w *= inv;
    v1.x *= inv; v1.y *= inv; v1.z *= inv; v1.w *= inv;
    *(float4*)(row + tid * 4) = v0;
    *(float4*)(row + 1024 + tid * 4) = v1;
}

// ---------------------------------------------------------------------------
extern "C" void kernel_launch(void* const* d_in, const int* in_sizes, int n_in,
                              void* d_out, int out_size)
{
    const float* x     = (const float*)d_in[0];   // [8,2048,768]
    const float* w_qkv = (const float*)d_in[1];   // [768,2304]
    const float* b_qkv = (const float*)d_in[2];   // [2304]
    const float* w_out = (const float*)d_in[3];   // [768,768]
    const float* b_out = (const float*)d_in[4];   // [768]
    float* out = (float*)d_out;                   // [8,2048,768]

    float *qkv_p = nullptr, *sc_p = nullptr, *att_p = nullptr;
    cudaGetSymbolAddress((void**)&qkv_p, g_qkv);
    cudaGetSymbolAddress((void**)&sc_p, g_scores);
    cudaGetSymbolAddress((void**)&att_p, g_att);

    const long long sQKV = (long long)SEQ * QKVO;   // per-batch qkv stride
    const long long sS   = (long long)SEQ * SEQ;
    const long long sO   = (long long)SEQ * DIM;

    // 1) QKV projection: [16384,768] @ [768,2304] + b_qkv
    gemm_kernel<false, true><<<dim3(QKVO / 128, BT / 128, 1), 256>>>(
        x, w_qkv, b_qkv, qkv_p, BT, QKVO, DIM, DIM, QKVO, QKVO, 1.0f, 0, 0, 0);

    // 2) S = 0.125 * Q @ K^T  per batch (NT; Q at +0, K at +768 in qkv rows)
    gemm_kernel<true, false><<<dim3(SEQ / 128, SEQ / 128, NB), 256>>>(
        qkv_p, qkv_p + DIM, nullptr, sc_p, SEQ, SEQ, DIM, QKVO, QKVO, SEQ,
        SCALE, sQKV, sQKV, sS);

    // 3) Row softmax in place
    softmax_kernel<<<NB * SEQ, 256>>>(sc_p);

    // 4) O = P @ V per batch (NN; V at +1536)
    gemm_kernel<false, false><<<dim3(DIM / 128, SEQ / 128, NB), 256>>>(
        sc_p, qkv_p + 2 * DIM, nullptr, att_p, SEQ, DIM, SEQ, SEQ, QKVO, DIM,
        1.0f, sS, sQKV, sO);

    // 5) Output projection: [16384,768] @ [768,768] + b_out
    gemm_kernel<false, true><<<dim3(DIM / 128, BT / 128, 1), 256>>>(
        att_p, w_out, b_out, out, BT, DIM, DIM, DIM, DIM, DIM, 1.0f, 0, 0, 0);
}

// round 6
// speedup vs baseline: 1.6355x; 1.6355x over previous
#include <cuda_runtime.h>
#include <cuda_bf16.h>
#include <math.h>
#include <stdint.h>

// B=8, T=2048, D=768, QKV_OUT=2304. Single-head attention over full 768 dims,
// scale 1/sqrt(64)=0.125. GEMMs: split-bf16 (hi+lo) 3-pass mma.sync m16n8k16.
#define BT 16384
#define DIM 768
#define QKVO 2304
#define SEQ 2048
#define NB 8
#define SCALE 0.125f

__device__ float g_qkv[(size_t)BT * QKVO];         // 16384 x 2304 (q|k|v)
__device__ float g_scores[(size_t)NB * SEQ * SEQ]; // 8 x 2048 x 2048
__device__ float g_att[(size_t)BT * DIM];          // 16384 x 768

// Split x into bf16 hi + bf16 lo, packed (lo<<16)|hi.
__device__ __forceinline__ uint32_t packsplit(float x) {
    __nv_bfloat16 h = __float2bfloat16(x);
    float hf = __bfloat162float(h);
    __nv_bfloat16 l = __float2bfloat16(x - hf);
    return ((uint32_t)__bfloat16_as_ushort(l) << 16) |
           (uint32_t)__bfloat16_as_ushort(h);
}

__device__ __forceinline__ uint32_t prmt(uint32_t a, uint32_t b, uint32_t sel) {
    uint32_t r;
    asm("prmt.b32 %0, %1, %2, %3;" : "=r"(r) : "r"(a), "r"(b), "r"(sel));
    return r;
}

__device__ __forceinline__ void mma_bf16(float* d, const uint32_t* a, const uint32_t* b) {
    asm volatile(
        "mma.sync.aligned.m16n8k16.row.col.f32.bf16.bf16.f32 "
        "{%0,%1,%2,%3}, {%4,%5,%6,%7}, {%8,%9}, {%0,%1,%2,%3};"
        : "+f"(d[0]), "+f"(d[1]), "+f"(d[2]), "+f"(d[3])
        : "r"(a[0]), "r"(a[1]), "r"(a[2]), "r"(a[3]), "r"(b[0]), "r"(b[1]));
}

// ---------------------------------------------------------------------------
// Split-bf16 tensor GEMM: C = alpha * A @ op(B) + bias.
// A [M,K] row-major. NN: B [K,N]; NT: B [N,K] (A@B^T).
// BM=BN=128, BK=32, 256 thr = 8 warps (2M x 4N), warp tile 64x32.
// Smem: packed hi|lo words. As[m][k] stride 36, Bs[k][n] stride 136.
// Per (im,jn) atom per k16: acc += ahi*bhi + ahi*blo + alo*bhi.
// ---------------------------------------------------------------------------
template<bool TRANSB, bool HASBIAS>
__global__ __launch_bounds__(256, 2)
void gemm_split_kernel(const float* __restrict__ A,
                       const float* __restrict__ B,
                       const float* __restrict__ bias,
                       float* __restrict__ C,
                       int M, int N, int K,
                       int lda, int ldb, int ldc,
                       float alpha,
                       long long sA, long long sB, long long sC)
{
    __shared__ __align__(16) uint32_t As[128 * 36];
    __shared__ __align__(16) uint32_t Bs[32 * 136];

    const int tid = threadIdx.x;
    const int lane = tid & 31;
    const int wid = tid >> 5;
    const int wm = (wid >> 2) * 64;
    const int wn = (wid & 3) * 32;
    const int lr = lane >> 2;   // 0..7
    const int lc = lane & 3;    // 0..3

    const float* Ab = A + (size_t)blockIdx.z * sA + (size_t)blockIdx.y * 128 * lda;
    const float* Bb;
    if (TRANSB)
        Bb = B + (size_t)blockIdx.z * sB + (size_t)blockIdx.x * 128 * ldb;
    else
        Bb = B + (size_t)blockIdx.z * sB + (size_t)blockIdx.x * 128;
    float* Cb = C + (size_t)blockIdx.z * sC;

    float acc[4][4][4];
#pragma unroll
    for (int i = 0; i < 4; i++)
#pragma unroll
        for (int j = 0; j < 4; j++)
#pragma unroll
            for (int q = 0; q < 4; q++) acc[i][j][q] = 0.0f;

    for (int k0 = 0; k0 < K; k0 += 32) {
        // ---- A tile 128x32 -> packed ----
        {
            int row = tid >> 1;
            int cq = (tid & 1) * 4;
#pragma unroll
            for (int it = 0; it < 4; it++) {
                int col = cq + it * 8;
                float4 v = *(const float4*)(Ab + (size_t)row * lda + k0 + col);
                uint32_t* d = As + row * 36 + col;
                d[0] = packsplit(v.x);
                d[1] = packsplit(v.y);
                d[2] = packsplit(v.z);
                d[3] = packsplit(v.w);
            }
        }
        // ---- B tile -> Bs[k][n] packed ----
        if (TRANSB) {
            int n = tid & 127;
            int kq = (tid >> 7) * 4;
#pragma unroll
            for (int it = 0; it < 4; it++) {
                int kb = kq + it * 8;
                float4 v = *(const float4*)(Bb + (size_t)n * ldb + k0 + kb);
                Bs[(kb + 0) * 136 + n] = packsplit(v.x);
                Bs[(kb + 1) * 136 + n] = packsplit(v.y);
                Bs[(kb + 2) * 136 + n] = packsplit(v.z);
                Bs[(kb + 3) * 136 + n] = packsplit(v.w);
            }
        } else {
#pragma unroll
            for (int it = 0; it < 4; it++) {
                int idx = tid + it * 256;
                int kk = idx >> 5;
                int nf = (idx & 31) * 4;
                float4 v = *(const float4*)(Bb + (size_t)(k0 + kk) * ldb + nf);
                uint32_t* d = Bs + kk * 136 + nf;
                d[0] = packsplit(v.x);
                d[1] = packsplit(v.y);
                d[2] = packsplit(v.z);
                d[3] = packsplit(v.w);
            }
        }
        __syncthreads();

        // ---- compute: 2 k16-steps ----
#pragma unroll
        for (int ks = 0; ks < 2; ks++) {
            int kb = ks * 16;
            // B fragments for 4 n-atoms
            uint32_t bh[4][2], bl[4][2];
#pragma unroll
            for (int jn = 0; jn < 4; jn++) {
                int n = wn + jn * 8 + lr;
                uint32_t w0 = Bs[(kb + 2 * lc + 0) * 136 + n];
                uint32_t w1 = Bs[(kb + 2 * lc + 1) * 136 + n];
                uint32_t w2 = Bs[(kb + 2 * lc + 8) * 136 + n];
                uint32_t w3 = Bs[(kb + 2 * lc + 9) * 136 + n];
                bh[jn][0] = prmt(w0, w1, 0x5410); bl[jn][0] = prmt(w0, w1, 0x7632);
                bh[jn][1] = prmt(w2, w3, 0x5410); bl[jn][1] = prmt(w2, w3, 0x7632);
            }
#pragma unroll
            for (int im = 0; im < 4; im++) {
                int r0 = wm + im * 16 + lr;
                uint2 q0 = *(const uint2*)(As + r0 * 36 + kb + 2 * lc);
                uint2 q1 = *(const uint2*)(As + (r0 + 8) * 36 + kb + 2 * lc);
                uint2 q2 = *(const uint2*)(As + r0 * 36 + kb + 2 * lc + 8);
                uint2 q3 = *(const uint2*)(As + (r0 + 8) * 36 + kb + 2 * lc + 8);
                uint32_t ah[4], al[4];
                ah[0] = prmt(q0.x, q0.y, 0x5410); al[0] = prmt(q0.x, q0.y, 0x7632);
                ah[1] = prmt(q1.x, q1.y, 0x5410); al[1] = prmt(q1.x, q1.y, 0x7632);
                ah[2] = prmt(q2.x, q2.y, 0x5410); al[2] = prmt(q2.x, q2.y, 0x7632);
                ah[3] = prmt(q3.x, q3.y, 0x5410); al[3] = prmt(q3.x, q3.y, 0x7632);
#pragma unroll
                for (int jn = 0; jn < 4; jn++) {
                    mma_bf16(acc[im][jn], ah, bh[jn]);   // hi*hi
                    mma_bf16(acc[im][jn], ah, bl[jn]);   // hi*lo
                    mma_bf16(acc[im][jn], al, bh[jn]);   // lo*hi
                }
            }
        }
        __syncthreads();
    }

    // ---- epilogue (m16n8 C layout: c0 (lr,2lc) c1 (lr,2lc+1) c2/c3 +8 rows) ----
#pragma unroll
    for (int im = 0; im < 4; im++) {
        int r0 = blockIdx.y * 128 + wm + im * 16 + lr;
#pragma unroll
        for (int jn = 0; jn < 4; jn++) {
            int c0 = blockIdx.x * 128 + wn + jn * 8 + 2 * lc;
            float bx = 0.0f, by = 0.0f;
            if (HASBIAS) { bx = bias[c0]; by = bias[c0 + 1]; }
            float2 v0, v1;
            v0.x = alpha * acc[im][jn][0] + bx;
            v0.y = alpha * acc[im][jn][1] + by;
            v1.x = alpha * acc[im][jn][2] + bx;
            v1.y = alpha * acc[im][jn][3] + by;
            *(float2*)(Cb + (size_t)r0 * ldc + c0) = v0;
            *(float2*)(Cb + (size_t)(r0 + 8) * ldc + c0) = v1;
        }
    }
}

// ---------------------------------------------------------------------------
// Row softmax in place: 16384 rows x 2048 cols. One block (256 thr) per row.
// ---------------------------------------------------------------------------
__global__ __launch_bounds__(256)
void softmax_kernel(float* __restrict__ S)
{
    __shared__ float red[8];
    int tid = threadIdx.x;
    float* row = S + (size_t)blockIdx.x * SEQ;

    float4 v0 = *(const float4*)(row + tid * 4);
    float4 v1 = *(const float4*)(row + 1024 + tid * 4);

    float mx = fmaxf(fmaxf(fmaxf(v0.x, v0.y), fmaxf(v0.z, v0.w)),
                     fmaxf(fmaxf(v1.x, v1.y), fmaxf(v1.z, v1.w)));
#pragma unroll
    for (int off = 16; off > 0; off >>= 1)
        mx = fmaxf(mx, __shfl_xor_sync(0xffffffffu, mx, off));
    if ((tid & 31) == 0) red[tid >> 5] = mx;
    __syncthreads();
    if (tid < 32) {
        float t = (tid < 8) ? red[tid] : -1e30f;
#pragma unroll
        for (int off = 4; off > 0; off >>= 1)
            t = fmaxf(t, __shfl_xor_sync(0xffffffffu, t, off));
        if (tid == 0) red[0] = t;
    }
    __syncthreads();
    mx = red[0];

    v0.x = __expf(v0.x - mx); v0.y = __expf(v0.y - mx);
    v0.z = __expf(v0.z - mx); v0.w = __expf(v0.w - mx);
    v1.x = __expf(v1.x - mx); v1.y = __expf(v1.y - mx);
    v1.z = __expf(v1.z - mx); v1.w = __expf(v1.w - mx);

    float sm = v0.x + v0.y + v0.z + v0.w + v1.x + v1.y + v1.z + v1.w;
#pragma unroll
    for (int off = 16; off > 0; off >>= 1)
        sm += __shfl_xor_sync(0xffffffffu, sm, off);
    if ((tid & 31) == 0) red[tid >> 5] = sm;
    __syncthreads();
    if (tid < 32) {
        float t = (tid < 8) ? red[tid] : 0.0f;
#pragma unroll
        for (int off = 4; off > 0; off >>= 1)
            t += __shfl_xor_sync(0xffffffffu, t, off);
        if (tid == 0) red[0] = t;
    }
    __syncthreads();
    float inv = 1.0f / red[0];

    v0.x *= inv; v0.y *= inv; v0.z *= inv; v0.w *= inv;
    v1.x *= inv; v1.y *= inv; v1.z *= inv; v1.w *= inv;
    *(float4*)(row + tid * 4) = v0;
    *(float4*)(row + 1024 + tid * 4) = v1;
}

// ---------------------------------------------------------------------------
extern "C" void kernel_launch(void* const* d_in, const int* in_sizes, int n_in,
                              void* d_out, int out_size)
{
    const float* x     = (const float*)d_in[0];   // [8,2048,768]
    const float* w_qkv = (const float*)d_in[1];   // [768,2304]
    const float* b_qkv = (const float*)d_in[2];   // [2304]
    const float* w_out = (const float*)d_in[3];   // [768,768]
    const float* b_out = (const float*)d_in[4];   // [768]
    float* out = (float*)d_out;                   // [8,2048,768]

    float *qkv_p = nullptr, *sc_p = nullptr, *att_p = nullptr;
    cudaGetSymbolAddress((void**)&qkv_p, g_qkv);
    cudaGetSymbolAddress((void**)&sc_p, g_scores);
    cudaGetSymbolAddress((void**)&att_p, g_att);

    const long long sQKV = (long long)SEQ * QKVO;
    const long long sS   = (long long)SEQ * SEQ;
    const long long sO   = (long long)SEQ * DIM;

    // 1) QKV projection: [16384,768] @ [768,2304] + b_qkv
    gemm_split_kernel<false, true><<<dim3(QKVO / 128, BT / 128, 1), 256>>>(
        x, w_qkv, b_qkv, qkv_p, BT, QKVO, DIM, DIM, QKVO, QKVO, 1.0f, 0, 0, 0);

    // 2) S = 0.125 * Q @ K^T per batch (NT; Q at +0, K at +768)
    gemm_split_kernel<true, false><<<dim3(SEQ / 128, SEQ / 128, NB), 256>>>(
        qkv_p, qkv_p + DIM, nullptr, sc_p, SEQ, SEQ, DIM, QKVO, QKVO, SEQ,
        SCALE, sQKV, sQKV, sS);

    // 3) Row softmax in place
    softmax_kernel<<<NB * SEQ, 256>>>(sc_p);

    // 4) O = P @ V per batch (NN; V at +1536)
    gemm_split_kernel<false, false><<<dim3(DIM / 128, SEQ / 128, NB), 256>>>(
        sc_p, qkv_p + 2 * DIM, nullptr, att_p, SEQ, DIM, SEQ, SEQ, QKVO, DIM,
        1.0f, sS, sQKV, sO);

    // 5) Output projection: [16384,768] @ [768,768] + b_out
    gemm_split_kernel<false, true><<<dim3(DIM / 128, BT / 128, 1), 256>>>(
        att_p, w_out, b_out, out, BT, DIM, DIM, DIM, DIM, DIM, 1.0f, 0, 0, 0);
}

// round 7
// speedup vs baseline: 1.6790x; 1.0266x over previous
#include <cuda_runtime.h>
#include <cuda_bf16.h>
#include <math.h>
#include <stdint.h>

// B=8, T=2048, D=768, QKV_OUT=2304. Single-head attention over full 768 dims,
// scale 1/sqrt(64)=0.125. Split-bf16 (hi+lo) 3-pass mma.sync m16n8k16 GEMMs,
// double-buffered smem pipeline, hi/lo plane layout (PRMT-free A/NT-B frags).
#define BT 16384
#define DIM 768
#define QKVO 2304
#define SEQ 2048
#define NB 8
#define SCALE 0.125f

__device__ float g_qkv[(size_t)BT * QKVO];         // 16384 x 2304 (q|k|v)
__device__ float g_scores[(size_t)NB * SEQ * SEQ]; // 8 x 2048 x 2048
__device__ float g_att[(size_t)BT * DIM];          // 16384 x 768

__device__ __forceinline__ void split1(float x, uint16_t& h, uint16_t& l) {
    __nv_bfloat16 hb = __float2bfloat16(x);
    h = __bfloat16_as_ushort(hb);
    l = __bfloat16_as_ushort(__float2bfloat16(x - __bfloat162float(hb)));
}
// word covering (k, k+1): low half = element at lower k
__device__ __forceinline__ uint32_t pck(uint16_t lo16, uint16_t hi16) {
    return ((uint32_t)hi16 << 16) | (uint32_t)lo16;
}
// packed single element: (lo<<16)|hi (R6 layout for NN B tiles)
__device__ __forceinline__ uint32_t packsplit(float x) {
    uint16_t h, l; split1(x, h, l);
    return ((uint32_t)l << 16) | (uint32_t)h;
}
__device__ __forceinline__ uint32_t prmt(uint32_t a, uint32_t b, uint32_t sel) {
    uint32_t r;
    asm("prmt.b32 %0, %1, %2, %3;" : "=r"(r) : "r"(a), "r"(b), "r"(sel));
    return r;
}
__device__ __forceinline__ void mma_bf16(float* d, const uint32_t* a, const uint32_t* b) {
    asm volatile(
        "mma.sync.aligned.m16n8k16.row.col.f32.bf16.bf16.f32 "
        "{%0,%1,%2,%3}, {%4,%5,%6,%7}, {%8,%9}, {%0,%1,%2,%3};"
        : "+f"(d[0]), "+f"(d[1]), "+f"(d[2]), "+f"(d[3])
        : "r"(a[0]), "r"(a[1]), "r"(a[2]), "r"(a[3]), "r"(b[0]), "r"(b[1]));
}

// Smem layout per buffer (uint32 units):
//   Ah: 128 rows x 20 words (stride 20 = 40 bf16)   [0, 2560)
//   Al:                                              [2560, 5120)
//   B region (union, 5120 words):
//     NT: Bh [n][k] 128x20 at +5120, Bl at +7680
//     NN: packed [k][n] 32x136 at +5120
#define BUFW 10240
#define GEMM_SMEM (2 * BUFW * 4)   // 81920 bytes

template<bool TRANSB, bool HASBIAS>
__global__ __launch_bounds__(512, 1)
void gemm_split_kernel(const float* __restrict__ A,
                       const float* __restrict__ B,
                       const float* __restrict__ bias,
                       float* __restrict__ C,
                       int M, int N, int K,
                       int lda, int ldb, int ldc,
                       float alpha,
                       long long sA, long long sB, long long sC)
{
    extern __shared__ __align__(16) uint32_t sm[];

    const int tid = threadIdx.x;
    const int lane = tid & 31;
    const int wid = tid >> 5;            // 0..15
    const int wm = (wid >> 2) * 32;      // warp M offset
    const int wn = (wid & 3) * 32;       // warp N offset
    const int lr = lane >> 2;            // 0..7
    const int lc = lane & 3;             // 0..3

    const float* Ab = A + (size_t)blockIdx.z * sA + (size_t)blockIdx.y * 128 * lda;
    const float* Bb;
    if (TRANSB)
        Bb = B + (size_t)blockIdx.z * sB + (size_t)blockIdx.x * 128 * ldb;
    else
        Bb = B + (size_t)blockIdx.z * sB + (size_t)blockIdx.x * 128;
    float* Cb = C + (size_t)blockIdx.z * sC;

    // loader indices: thread -> (row 0..127, col-quad of 8)
    const int a_row = tid >> 2;
    const int a_cq = (tid & 3) * 8;
    // NN B loader: 2 slots of (kk, nf)
    const int nn_kk0 = tid >> 5;           // 0..15
    const int nn_kk1 = nn_kk0 + 16;        // 16..31
    const int nn_nf = (tid & 31) * 4;

    float acc[2][4][4];
#pragma unroll
    for (int i = 0; i < 2; i++)
#pragma unroll
        for (int j = 0; j < 4; j++)
#pragma unroll
            for (int q = 0; q < 4; q++) acc[i][j][q] = 0.0f;

    float4 pa0, pa1, pb0, pb1;

    auto load_tile = [&](int k0) {
        const float* ap = Ab + (size_t)a_row * lda + k0 + a_cq;
        pa0 = *(const float4*)(ap);
        pa1 = *(const float4*)(ap + 4);
        if (TRANSB) {
            const float* bp = Bb + (size_t)a_row * ldb + k0 + a_cq;
            pb0 = *(const float4*)(bp);
            pb1 = *(const float4*)(bp + 4);
        } else {
            pb0 = *(const float4*)(Bb + (size_t)(k0 + nn_kk0) * ldb + nn_nf);
            pb1 = *(const float4*)(Bb + (size_t)(k0 + nn_kk1) * ldb + nn_nf);
        }
    };

    auto store_tile = [&](int bsel) {
        uint32_t* base = sm + bsel * BUFW;
        uint16_t h[8], l[8];
        split1(pa0.x, h[0], l[0]); split1(pa0.y, h[1], l[1]);
        split1(pa0.z, h[2], l[2]); split1(pa0.w, h[3], l[3]);
        split1(pa1.x, h[4], l[4]); split1(pa1.y, h[5], l[5]);
        split1(pa1.z, h[6], l[6]); split1(pa1.w, h[7], l[7]);
        int aw = a_row * 20 + (a_cq >> 1);
        *(uint4*)&base[aw] = make_uint4(pck(h[0], h[1]), pck(h[2], h[3]),
                                        pck(h[4], h[5]), pck(h[6], h[7]));
        *(uint4*)&base[2560 + aw] = make_uint4(pck(l[0], l[1]), pck(l[2], l[3]),
                                               pck(l[4], l[5]), pck(l[6], l[7]));
        if (TRANSB) {
            split1(pb0.x, h[0], l[0]); split1(pb0.y, h[1], l[1]);
            split1(pb0.z, h[2], l[2]); split1(pb0.w, h[3], l[3]);
            split1(pb1.x, h[4], l[4]); split1(pb1.y, h[5], l[5]);
            split1(pb1.z, h[6], l[6]); split1(pb1.w, h[7], l[7]);
            *(uint4*)&base[5120 + aw] = make_uint4(pck(h[0], h[1]), pck(h[2], h[3]),
                                                   pck(h[4], h[5]), pck(h[6], h[7]));
            *(uint4*)&base[7680 + aw] = make_uint4(pck(l[0], l[1]), pck(l[2], l[3]),
                                                   pck(l[4], l[5]), pck(l[6], l[7]));
        } else {
            uint32_t* Bp = base + 5120;
            *(uint4*)&Bp[nn_kk0 * 136 + nn_nf] =
                make_uint4(packsplit(pb0.x), packsplit(pb0.y),
                           packsplit(pb0.z), packsplit(pb0.w));
            *(uint4*)&Bp[nn_kk1 * 136 + nn_nf] =
                make_uint4(packsplit(pb1.x), packsplit(pb1.y),
                           packsplit(pb1.z), packsplit(pb1.w));
        }
    };

    const int niter = K >> 5;

    // prologue
    load_tile(0);
    store_tile(0);
    __syncthreads();

    for (int it = 0; it < niter; it++) {
        if (it + 1 < niter) load_tile((it + 1) * 32);

        const uint32_t* Ah = sm + (it & 1) * BUFW;
        const uint32_t* Al = Ah + 2560;

#pragma unroll
        for (int ks = 0; ks < 2; ks++) {
            const int kw = ks * 8;   // word offset within tile (k16 step)
            uint32_t bh[4][2], bl[4][2];
            if (TRANSB) {
                const uint32_t* Bh = sm + (it & 1) * BUFW + 5120;
                const uint32_t* Bl = Bh + 2560;
#pragma unroll
                for (int jn = 0; jn < 4; jn++) {
                    int n = wn + jn * 8 + lr;
                    bh[jn][0] = Bh[n * 20 + kw + lc];
                    bh[jn][1] = Bh[n * 20 + kw + lc + 4];
                    bl[jn][0] = Bl[n * 20 + kw + lc];
                    bl[jn][1] = Bl[n * 20 + kw + lc + 4];
                }
            } else {
                const uint32_t* Bp = sm + (it & 1) * BUFW + 5120;
                const int kb = ks * 16;
#pragma unroll
                for (int jn = 0; jn < 4; jn++) {
                    int n = wn + jn * 8 + lr;
                    uint32_t w0 = Bp[(kb + 2 * lc + 0) * 136 + n];
                    uint32_t w1 = Bp[(kb + 2 * lc + 1) * 136 + n];
                    uint32_t w2 = Bp[(kb + 2 * lc + 8) * 136 + n];
                    uint32_t w3 = Bp[(kb + 2 * lc + 9) * 136 + n];
                    bh[jn][0] = prmt(w0, w1, 0x5410); bl[jn][0] = prmt(w0, w1, 0x7632);
                    bh[jn][1] = prmt(w2, w3, 0x5410); bl[jn][1] = prmt(w2, w3, 0x7632);
                }
            }
#pragma unroll
            for (int im = 0; im < 2; im++) {
                int r0 = wm + im * 16 + lr;
                uint32_t ah[4], al[4];
                ah[0] = Ah[r0 * 20 + kw + lc];
                ah[1] = Ah[(r0 + 8) * 20 + kw + lc];
                ah[2] = Ah[r0 * 20 + kw + lc + 4];
                ah[3] = Ah[(r0 + 8) * 20 + kw + lc + 4];
                al[0] = Al[r0 * 20 + kw + lc];
                al[1] = Al[(r0 + 8) * 20 + kw + lc];
                al[2] = Al[r0 * 20 + kw + lc + 4];
                al[3] = Al[(r0 + 8) * 20 + kw + lc + 4];
#pragma unroll
                for (int jn = 0; jn < 4; jn++) {
                    mma_bf16(acc[im][jn], ah, bh[jn]);   // hi*hi
                    mma_bf16(acc[im][jn], ah, bl[jn]);   // hi*lo
                    mma_bf16(acc[im][jn], al, bh[jn]);   // lo*hi
                }
            }
        }

        if (it + 1 < niter) store_tile((it + 1) & 1);
        __syncthreads();
    }

    // epilogue (m16n8 C layout, verified R6)
#pragma unroll
    for (int im = 0; im < 2; im++) {
        int r0 = blockIdx.y * 128 + wm + im * 16 + lr;
#pragma unroll
        for (int jn = 0; jn < 4; jn++) {
            int c0 = blockIdx.x * 128 + wn + jn * 8 + 2 * lc;
            float bx = 0.0f, by = 0.0f;
            if (HASBIAS) { bx = bias[c0]; by = bias[c0 + 1]; }
            float2 v0, v1;
            v0.x = alpha * acc[im][jn][0] + bx;
            v0.y = alpha * acc[im][jn][1] + by;
            v1.x = alpha * acc[im][jn][2] + bx;
            v1.y = alpha * acc[im][jn][3] + by;
            *(float2*)(Cb + (size_t)r0 * ldc + c0) = v0;
            *(float2*)(Cb + (size_t)(r0 + 8) * ldc + c0) = v1;
        }
    }
}

// ---------------------------------------------------------------------------
// Row softmax in place: 16384 rows x 2048 cols. One block (256 thr) per row.
// ---------------------------------------------------------------------------
__global__ __launch_bounds__(256)
void softmax_kernel(float* __restrict__ S)
{
    __shared__ float red[8];
    int tid = threadIdx.x;
    float* row = S + (size_t)blockIdx.x * SEQ;

    float4 v0 = *(const float4*)(row + tid * 4);
    float4 v1 = *(const float4*)(row + 1024 + tid * 4);

    float mx = fmaxf(fmaxf(fmaxf(v0.x, v0.y), fmaxf(v0.z, v0.w)),
                     fmaxf(fmaxf(v1.x, v1.y), fmaxf(v1.z, v1.w)));
#pragma unroll
    for (int off = 16; off > 0; off >>= 1)
        mx = fmaxf(mx, __shfl_xor_sync(0xffffffffu, mx, off));
    if ((tid & 31) == 0) red[tid >> 5] = mx;
    __syncthreads();
    if (tid < 32) {
        float t = (tid < 8) ? red[tid] : -1e30f;
#pragma unroll
        for (int off = 4; off > 0; off >>= 1)
            t = fmaxf(t, __shfl_xor_sync(0xffffffffu, t, off));
        if (tid == 0) red[0] = t;
    }
    __syncthreads();
    mx = red[0];

    v0.x = __expf(v0.x - mx); v0.y = __expf(v0.y - mx);
    v0.z = __expf(v0.z - mx); v0.w = __expf(v0.w - mx);
    v1.x = __expf(v1.x - mx); v1.y = __expf(v1.y - mx);
    v1.z = __expf(v1.z - mx); v1.w = __expf(v1.w - mx);

    float sm_ = v0.x + v0.y + v0.z + v0.w + v1.x + v1.y + v1.z + v1.w;
#pragma unroll
    for (int off = 16; off > 0; off >>= 1)
        sm_ += __shfl_xor_sync(0xffffffffu, sm_, off);
    if ((tid & 31) == 0) red[tid >> 5] = sm_;
    __syncthreads();
    if (tid < 32) {
        float t = (tid < 8) ? red[tid] : 0.0f;
#pragma unroll
        for (int off = 4; off > 0; off >>= 1)
            t += __shfl_xor_sync(0xffffffffu, t, off);
        if (tid == 0) red[0] = t;
    }
    __syncthreads();
    float inv = 1.0f / red[0];

    v0.x *= inv; v0.y *= inv; v0.z *= inv; v0.w *= inv;
    v1.x *= inv; v1.y *= inv; v1.z *= inv; v1.w *= inv;
    *(float4*)(row + tid * 4) = v0;
    *(float4*)(row + 1024 + tid * 4) = v1;
}

// ---------------------------------------------------------------------------
extern "C" void kernel_launch(void* const* d_in, const int* in_sizes, int n_in,
                              void* d_out, int out_size)
{
    const float* x     = (const float*)d_in[0];   // [8,2048,768]
    const float* w_qkv = (const float*)d_in[1];   // [768,2304]
    const float* b_qkv = (const float*)d_in[2];   // [2304]
    const float* w_out = (const float*)d_in[3];   // [768,768]
    const float* b_out = (const float*)d_in[4];   // [768]
    float* out = (float*)d_out;                   // [8,2048,768]

    float *qkv_p = nullptr, *sc_p = nullptr, *att_p = nullptr;
    cudaGetSymbolAddress((void**)&qkv_p, g_qkv);
    cudaGetSymbolAddress((void**)&sc_p, g_scores);
    cudaGetSymbolAddress((void**)&att_p, g_att);

    cudaFuncSetAttribute(gemm_split_kernel<false, true>,
                         cudaFuncAttributeMaxDynamicSharedMemorySize, GEMM_SMEM);
    cudaFuncSetAttribute(gemm_split_kernel<true, false>,
                         cudaFuncAttributeMaxDynamicSharedMemorySize, GEMM_SMEM);
    cudaFuncSetAttribute(gemm_split_kernel<false, false>,
                         cudaFuncAttributeMaxDynamicSharedMemorySize, GEMM_SMEM);

    const long long sQKV = (long long)SEQ * QKVO;
    const long long sS   = (long long)SEQ * SEQ;
    const long long sO   = (long long)SEQ * DIM;

    // 1) QKV projection: [16384,768] @ [768,2304] + b_qkv
    gemm_split_kernel<false, true><<<dim3(QKVO / 128, BT / 128, 1), 512, GEMM_SMEM>>>(
        x, w_qkv, b_qkv, qkv_p, BT, QKVO, DIM, DIM, QKVO, QKVO, 1.0f, 0, 0, 0);

    // 2) S = 0.125 * Q @ K^T per batch (NT; Q at +0, K at +768)
    gemm_split_kernel<true, false><<<dim3(SEQ / 128, SEQ / 128, NB), 512, GEMM_SMEM>>>(
        qkv_p, qkv_p + DIM, nullptr, sc_p, SEQ, SEQ, DIM, QKVO, QKVO, SEQ,
        SCALE, sQKV, sQKV, sS);

    // 3) Row softmax in place
    softmax_kernel<<<NB * SEQ, 256>>>(sc_p);

    // 4) O = P @ V per batch (NN; V at +1536)
    gemm_split_kernel<false, false><<<dim3(DIM / 128, SEQ / 128, NB), 512, GEMM_SMEM>>>(
        sc_p, qkv_p + 2 * DIM, nullptr, att_p, SEQ, DIM, SEQ, SEQ, QKVO, DIM,
        1.0f, sS, sQKV, sO);

    // 5) Output projection: [16384,768] @ [768,768] + b_out
    gemm_split_kernel<false, true><<<dim3(DIM / 128, BT / 128, 1), 512, GEMM_SMEM>>>(
        att_p, w_out, b_out, out, BT, DIM, DIM, DIM, DIM, DIM, 1.0f, 0, 0, 0);
}

// round 11
// speedup vs baseline: 1.9432x; 1.1574x over previous
#include <cuda_runtime.h>
#include <cuda_bf16.h>
#include <stdint.h>

// B=8, T=2048, D=768, QKV_OUT=2304. Single-head attention over full 768 dims,
// scale 1/sqrt(64)=0.125. All GEMMs NT on mma.sync bf16 (split hi/lo 3-pass),
// ldmatrix fragment loads, 256thr x 2CTA/SM, warp tile 64x32.
#define BT 16384
#define DIM 768
#define QKVO 2304
#define SEQ 2048
#define NB 8
#define SCALE 0.125f

__device__ float g_qkv[(size_t)BT * QKVO];          // 16384 x 2304 (q|k|v)
__device__ float g_scores[(size_t)NB * SEQ * SEQ];  // 8 x 2048 x 2048
__device__ float g_att[(size_t)BT * DIM];           // 16384 x 768
__device__ float g_wqkvT[(size_t)QKVO * DIM];       // 2304 x 768
__device__ float g_woutT[(size_t)DIM * DIM];        // 768 x 768
__device__ float g_vT[(size_t)NB * DIM * SEQ];      // 8 x 768 x 2048

// split (x lower-k, y upper-k) -> packed hi word, lo word (low half = lower k)
__device__ __forceinline__ void split2(float x, float y, uint32_t& h, uint32_t& l) {
    __nv_bfloat16 hx = __float2bfloat16(x), hy = __float2bfloat16(y);
    __nv_bfloat16 lx = __float2bfloat16(x - __bfloat162float(hx));
    __nv_bfloat16 ly = __float2bfloat16(y - __bfloat162float(hy));
    h = ((uint32_t)__bfloat16_as_ushort(hy) << 16) | (uint32_t)__bfloat16_as_ushort(hx);
    l = ((uint32_t)__bfloat16_as_ushort(ly) << 16) | (uint32_t)__bfloat16_as_ushort(lx);
}
__device__ __forceinline__ void mma_bf16(float* d, const uint32_t* a, const uint32_t* b) {
    asm volatile(
        "mma.sync.aligned.m16n8k16.row.col.f32.bf16.bf16.f32 "
        "{%0,%1,%2,%3}, {%4,%5,%6,%7}, {%8,%9}, {%0,%1,%2,%3};"
        : "+f"(d[0]), "+f"(d[1]), "+f"(d[2]), "+f"(d[3])
        : "r"(a[0]), "r"(a[1]), "r"(a[2]), "r"(a[3]), "r"(b[0]), "r"(b[1]));
}
#define LDSM_X4(r0, r1, r2, r3, addr) \
    asm volatile("ldmatrix.sync.aligned.m8n8.x4.shared.b16 {%0,%1,%2,%3}, [%4];" \
        : "=r"(r0), "=r"(r1), "=r"(r2), "=r"(r3) : "r"(addr))

// Plane layout: [row][k] rows of 40 bf16 (80 B), rows = m (A) or n (B).
// Per-buffer planes (bytes): Ah 10240 | Al 10240 | Bh 10240 | Bl 10240.
#define PLANE 10240
#define ROWB 80

// ---------------------------------------------------------------------------
// NT GEMM: C[M,N] = alpha * A[M,K] @ B[N,K]^T (+bias). Batched via grid.z.
// BM=BN=128, BK=32. 256 threads = 8 warps (2M x 4N), warp tile 64x32.
// Single smem buffer (40KB static), 2 CTAs/SM.
// ---------------------------------------------------------------------------
__global__ __launch_bounds__(256, 2)
void gemm_nt(const float* __restrict__ A, const float* __restrict__ B,
             const float* __restrict__ bias, float* __restrict__ C,
             int K, int lda, int ldb, int ldc, float alpha,
             long long sA, long long sB, long long sC)
{
    __shared__ __align__(16) char smem[4 * PLANE];

    const int tid = threadIdx.x;
    const int lane = tid & 31;
    const int wid = tid >> 5;
    const int wm = (wid >> 2) * 64;     // 0 / 64
    const int wn = (wid & 3) * 32;      // 0/32/64/96
    const int lr = lane >> 2;           // 0..7
    const int lc = lane & 3;            // 0..3

    const uint32_t sbase = (uint32_t)__cvta_generic_to_shared(smem);
    // ldmatrix lane offset: i = lane&7, j = lane>>3
    const int lm_i = lane & 7, lm_j = lane >> 3;
    const uint32_t laneoff = (uint32_t)((lm_i + (lm_j & 1) * 8) * ROWB + (lm_j >> 1) * 16);

    const float* Ap = A + (size_t)blockIdx.z * sA + (size_t)blockIdx.y * 128 * lda;
    const float* Bp = B + (size_t)blockIdx.z * sB + (size_t)blockIdx.x * 128 * ldb;
    float* Cb = C + (size_t)blockIdx.z * sC;

    // loader: thread -> row (0..127), col quad base (0 or 16)
    const int ld_row = tid >> 1;
    const int ld_c0 = (tid & 1) * 16;

    float acc[4][4][4];
#pragma unroll
    for (int i = 0; i < 4; i++)
#pragma unroll
        for (int j = 0; j < 4; j++)
#pragma unroll
            for (int q = 0; q < 4; q++) acc[i][j][q] = 0.0f;

    const int nc = K >> 5;
    for (int ch = 0; ch < nc; ch++) {
        const int k0 = ch << 5;
        __syncthreads();   // previous compute done before overwrite
        // ---- load + convert A (rows=m) and B (rows=n) into planes ----
        {
            const float* ar = Ap + (size_t)ld_row * lda + k0 + ld_c0;
            const float* br = Bp + (size_t)ld_row * ldb + k0 + ld_c0;
            char* Ah = smem;
            char* Al = smem + PLANE;
            char* Bh = smem + 2 * PLANE;
            char* Bl = smem + 3 * PLANE;
            int wo = ld_row * ROWB + ld_c0 * 2;   // byte offset of col ld_c0
#pragma unroll
            for (int q = 0; q < 4; q++) {
                float4 v = *(const float4*)(ar + q * 4);
                uint2 h, l;
                split2(v.x, v.y, h.x, l.x);
                split2(v.z, v.w, h.y, l.y);
                *(uint2*)(Ah + wo + q * 8) = h;
                *(uint2*)(Al + wo + q * 8) = l;
            }
#pragma unroll
            for (int q = 0; q < 4; q++) {
                float4 v = *(const float4*)(br + q * 4);
                uint2 h, l;
                split2(v.x, v.y, h.x, l.x);
                split2(v.z, v.w, h.y, l.y);
                *(uint2*)(Bh + wo + q * 8) = h;
                *(uint2*)(Bl + wo + q * 8) = l;
            }
        }
        __syncthreads();

        // ---- compute: 2 k16 steps ----
#pragma unroll
        for (int ks = 0; ks < 2; ks++) {
            const uint32_t kboff = (uint32_t)(ks * 32);   // 16 bf16 = 32 B
            // B fragments: 2 x4 per plane cover n 0..31 of this warp
            uint32_t bh[4][2], bl[4][2];
#pragma unroll
            for (int q = 0; q < 2; q++) {
                uint32_t ba = sbase + 2 * PLANE + (uint32_t)((wn + q * 16) * ROWB)
                              + laneoff + kboff;
                uint32_t r0, r1, r2, r3;
                LDSM_X4(r0, r1, r2, r3, ba);
                bh[q * 2 + 0][0] = r0; bh[q * 2 + 1][0] = r1;
                bh[q * 2 + 0][1] = r2; bh[q * 2 + 1][1] = r3;
                uint32_t bb = ba + PLANE;
                LDSM_X4(r0, r1, r2, r3, bb);
                bl[q * 2 + 0][0] = r0; bl[q * 2 + 1][0] = r1;
                bl[q * 2 + 0][1] = r2; bl[q * 2 + 1][1] = r3;
            }
#pragma unroll
            for (int im = 0; im < 4; im++) {
                uint32_t aa = sbase + (uint32_t)((wm + im * 16) * ROWB)
                              + laneoff + kboff;
                uint32_t ah[4], al[4];
                LDSM_X4(ah[0], ah[1], ah[2], ah[3], aa);
                LDSM_X4(al[0], al[1], al[2], al[3], aa + PLANE);
#pragma unroll
                for (int jn = 0; jn < 4; jn++) {
                    mma_bf16(acc[im][jn], ah, bh[jn]);   // hi*hi
                    mma_bf16(acc[im][jn], ah, bl[jn]);   // hi*lo
                    mma_bf16(acc[im][jn], al, bh[jn]);   // lo*hi
                }
            }
        }
    }

    // ---- epilogue (verified R6/R7 m16n8 C mapping) ----
#pragma unroll
    for (int im = 0; im < 4; im++) {
        int r0 = blockIdx.y * 128 + wm + im * 16 + lr;
#pragma unroll
        for (int jn = 0; jn < 4; jn++) {
            int c0 = blockIdx.x * 128 + wn + jn * 8 + 2 * lc;
            float bx = 0.0f, by = 0.0f;
            if (bias) { bx = bias[c0]; by = bias[c0 + 1]; }
            float2 v0, v1;
            v0.x = alpha * acc[im][jn][0] + bx;
            v0.y = alpha * acc[im][jn][1] + by;
            v1.x = alpha * acc[im][jn][2] + bx;
            v1.y = alpha * acc[im][jn][3] + by;
            *(float2*)(Cb + (size_t)r0 * ldc + c0) = v0;
            *(float2*)(Cb + (size_t)(r0 + 8) * ldc + c0) = v1;
        }
    }
}

// ---------------------------------------------------------------------------
// Batched strided 32x32 tiled transpose: dst[c][r] = src[r][c].
// ---------------------------------------------------------------------------
__global__ __launch_bounds__(256)
void transpose_kernel(const float* __restrict__ src, float* __restrict__ dst,
                      int lds, int ldd, long long sS, long long sD)
{
    __shared__ float t[32][33];
    src += (size_t)blockIdx.z * sS;
    dst += (size_t)blockIdx.z * sD;
    int r0 = blockIdx.y * 32, c0 = blockIdx.x * 32;
    int tx = threadIdx.x & 31, ty = threadIdx.x >> 5;   // 32 x 8
#pragma unroll
    for (int i = ty; i < 32; i += 8)
        t[i][tx] = src[(size_t)(r0 + i) * lds + c0 + tx];
    __syncthreads();
#pragma unroll
    for (int i = ty; i < 32; i += 8)
        dst[(size_t)(c0 + i) * ldd + r0 + tx] = t[tx][i];
}

// ---------------------------------------------------------------------------
// Row softmax in place: 16384 rows x 2048 cols. One block (256 thr) per row.
// ---------------------------------------------------------------------------
__global__ __launch_bounds__(256)
void softmax_kernel(float* __restrict__ S)
{
    __shared__ float red[8];
    int tid = threadIdx.x;
    float* row = S + (size_t)blockIdx.x * SEQ;

    float4 v0 = *(const float4*)(row + tid * 4);
    float4 v1 = *(const float4*)(row + 1024 + tid * 4);

    float mx = fmaxf(fmaxf(fmaxf(v0.x, v0.y), fmaxf(v0.z, v0.w)),
                     fmaxf(fmaxf(v1.x, v1.y), fmaxf(v1.z, v1.w)));
#pragma unroll
    for (int off = 16; off > 0; off >>= 1)
        mx = fmaxf(mx, __shfl_xor_sync(0xffffffffu, mx, off));
    if ((tid & 31) == 0) red[tid >> 5] = mx;
    __syncthreads();
    if (tid < 32) {
        float t = (tid < 8) ? red[tid] : -1e30f;
#pragma unroll
        for (int off = 4; off > 0; off >>= 1)
            t = fmaxf(t, __shfl_xor_sync(0xffffffffu, t, off));
        if (tid == 0) red[0] = t;
    }
    __syncthreads();
    mx = red[0];

    v0.x = __expf(v0.x - mx); v0.y = __expf(v0.y - mx);
    v0.z = __expf(v0.z - mx); v0.w = __expf(v0.w - mx);
    v1.x = __expf(v1.x - mx); v1.y = __expf(v1.y - mx);
    v1.z = __expf(v1.z - mx); v1.w = __expf(v1.w - mx);

    float sm_ = v0.x + v0.y + v0.z + v0.w + v1.x + v1.y + v1.z + v1.w;
#pragma unroll
    for (int off = 16; off > 0; off >>= 1)
        sm_ += __shfl_xor_sync(0xffffffffu, sm_, off);
    if ((tid & 31) == 0) red[tid >> 5] = sm_;
    __syncthreads();
    if (tid < 32) {
        float t = (tid < 8) ? red[tid] : 0.0f;
#pragma unroll
        for (int off = 4; off > 0; off >>= 1)
            t += __shfl_xor_sync(0xffffffffu, t, off);
        if (tid == 0) red[0] = t;
    }
    __syncthreads();
    float inv = 1.0f / red[0];

    v0.x *= inv; v0.y *= inv; v0.z *= inv; v0.w *= inv;
    v1.x *= inv; v1.y *= inv; v1.z *= inv; v1.w *= inv;
    *(float4*)(row + tid * 4) = v0;
    *(float4*)(row + 1024 + tid * 4) = v1;
}

// ---------------------------------------------------------------------------
extern "C" void kernel_launch(void* const* d_in, const int* in_sizes, int n_in,
                              void* d_out, int out_size)
{
    const float* x     = (const float*)d_in[0];   // [8,2048,768]
    const float* w_qkv = (const float*)d_in[1];   // [768,2304]
    const float* b_qkv = (const float*)d_in[2];   // [2304]
    const float* w_out = (const float*)d_in[3];   // [768,768]
    const float* b_out = (const float*)d_in[4];   // [768]
    float* out = (float*)d_out;                   // [8,2048,768]

    float *qkv_p, *sc_p, *att_p, *wqT, *woT, *vT;
    cudaGetSymbolAddress((void**)&qkv_p, g_qkv);
    cudaGetSymbolAddress((void**)&sc_p, g_scores);
    cudaGetSymbolAddress((void**)&att_p, g_att);
    cudaGetSymbolAddress((void**)&wqT, g_wqkvT);
    cudaGetSymbolAddress((void**)&woT, g_woutT);
    cudaGetSymbolAddress((void**)&vT, g_vT);

    const long long sQKV = (long long)SEQ * QKVO;
    const long long sS   = (long long)SEQ * SEQ;
    const long long sO   = (long long)SEQ * DIM;
    const long long sVT  = (long long)DIM * SEQ;

    // 0a) w_qkv [768,2304] -> w_qkvT [2304,768]
    transpose_kernel<<<dim3(QKVO / 32, DIM / 32, 1), 256>>>(
        w_qkv, wqT, QKVO, DIM, 0, 0);
    // 0b) w_out [768,768] -> w_outT
    transpose_kernel<<<dim3(DIM / 32, DIM / 32, 1), 256>>>(
        w_out, woT, DIM, DIM, 0, 0);

    // 1) QKV projection: x @ w_qkvT^T + b_qkv   (M=16384, N=2304, K=768)
    gemm_nt<<<dim3(QKVO / 128, BT / 128, 1), 256>>>(
        x, wqT, b_qkv, qkv_p, DIM, DIM, DIM, QKVO, 1.0f, 0, 0, 0);

    // 1b) V (rows of qkv, +1536) -> vT [768,2048] per batch
    transpose_kernel<<<dim3(DIM / 32, SEQ / 32, NB), 256>>>(
        qkv_p + 2 * DIM, vT, QKVO, SEQ, sQKV, sVT);

    // 2) S = 0.125 * Q @ K^T per batch (M=N=2048, K=768)
    gemm_nt<<<dim3(SEQ / 128, SEQ / 128, NB), 256>>>(
        qkv_p, qkv_p + DIM, nullptr, sc_p, DIM, QKVO, QKVO, SEQ,
        SCALE, sQKV, sQKV, sS);

    // 3) Row softmax in place
    softmax_kernel<<<NB * SEQ, 256>>>(sc_p);

    // 4) O = P @ vT^T per batch (M=2048, N=768, K=2048)
    gemm_nt<<<dim3(DIM / 128, SEQ / 128, NB), 256>>>(
        sc_p, vT, nullptr, att_p, SEQ, SEQ, SEQ, DIM, 1.0f, sS, sVT, sO);

    // 5) Output projection: att @ w_outT^T + b_out (M=16384, N=768, K=768)
    gemm_nt<<<dim3(DIM / 128, BT / 128, 1), 256>>>(
        att_p, woT, b_out, out, DIM, DIM, DIM, DIM, 1.0f, 0, 0, 0);
}